// round 5
// baseline (speedup 1.0000x reference)
#include <cuda_runtime.h>
#include <cstdint>

// PatchNeighborSearcher: B=8, H=W=16 (P=256), L=64, C=64.
// out[b, p, l*8+n, c] = in[b, neighbor_p(n), l, c] if in-bounds else 0.
//
// Loads: per-thread 8 predicated LDG.128 (MLP=8), dedup in L1/L2.
// Stores: staged in SMEM, drained via cp.async.bulk shared->global (TMA path),
// bypassing the L1tex store wavefront pipe entirely.
//
// Block = fixed (b, l, h); threads = 16 w x 16 c4.
// Input  float4 idx: (b<<18)|(h<<14)|(w<<10)|(l<<4)|c4
// Output float4 idx: (b<<21)|(h<<17)|(w<<13)|(l<<7)|(n<<4)|c4
//   -> for fixed (b,h,w,l): [n][c4] = 128 float4 = 2KB contiguous.

__global__ void __launch_bounds__(256) patch_neighbor_kernel(
    const float4* __restrict__ in, float4* __restrict__ out)
{
    __shared__ float4 tile[16][8][16];   // [w][n][c4] = 32 KB

    int bid = blockIdx.x;                // (b<<10)|(l<<4)|h
    int h = bid & 15;
    int l = (bid >> 4) & 63;
    int b = bid >> 10;

    int c4 = threadIdx.x & 15;
    int w  = threadIdx.x >> 4;

    int hm = (h > 0);
    int hp = (h < 15);
    int wm = (w > 0);
    int wp = (w < 15);

    // neighbor order: (-1,-1)(-1,0)(-1,1)(0,-1)(0,1)(1,-1)(1,0)(1,1)
    int valid[8] = { hm & wm, hm, hm & wp,
                     wm,          wp,
                     hp & wm, hp, hp & wp };

    // neighbor offset in float4 units: (dy*16 + dx) << 10
    constexpr int OFF[8] = {
        (-17) << 10, (-16) << 10, (-15) << 10,
        ( -1) << 10,               (  1) << 10,
        ( 15) << 10, ( 16) << 10, ( 17) << 10
    };

    int ibase = (b << 18) | (h << 14) | (w << 10) | (l << 4) | c4;

    const float4 zero = make_float4(0.f, 0.f, 0.f, 0.f);

    #pragma unroll
    for (int n = 0; n < 8; n++) {
        tile[w][n][c4] = valid[n] ? __ldg(&in[ibase + OFF[n]]) : zero;
    }

    __syncthreads();

    if (threadIdx.x < 16) {
        int ww = threadIdx.x;
        // make SMEM writes (generic proxy) visible to the async proxy
        asm volatile("fence.proxy.async.shared::cta;" ::: "memory");

        int obase = (b << 21) | (h << 17) | (ww << 13) | (l << 7);
        uint32_t saddr;
        asm("{ .reg .u64 t; cvta.to.shared.u64 t, %1; cvt.u32.u64 %0, t; }"
            : "=r"(saddr) : "l"(&tile[ww][0][0]));

        asm volatile(
            "cp.async.bulk.global.shared::cta.bulk_group [%0], [%1], 2048;"
            :: "l"(out + obase), "r"(saddr) : "memory");

        asm volatile("cp.async.bulk.commit_group;" ::: "memory");
        asm volatile("cp.async.bulk.wait_group 0;" ::: "memory");
    }
}

extern "C" void kernel_launch(void* const* d_in, const int* in_sizes, int n_in,
                              void* d_out, int out_size)
{
    const float4* in = (const float4*)d_in[0];
    float4* out = (float4*)d_out;

    int grid = 8 * 64 * 16;   // (b, l, h) = 8192 blocks
    patch_neighbor_kernel<<<grid, 256>>>(in, out);
}

// round 6
// speedup vs baseline: 1.0423x; 1.0423x over previous
#include <cuda_runtime.h>
#include <cstdint>

// PatchNeighborSearcher: B=8, H=W=16 (P=256), L=64, C=64.
// out[b, p, l*8+n, c] = in[b, neighbor_p(n), l, c] if in-bounds else 0.
//
// SMEM-staged loads: each block (b, l, h-pair) loads its 4 input h-rows
// (2 output rows + halo, zero-filled at borders) into SMEM exactly once,
// then emits all 8-neighbor outputs from SMEM. Global load traffic drops
// ~3x vs the gather versions; stores remain perfectly coalesced streaming.
//
// Block: 128 threads. grid = 8b * 64l * 8hp = 4096.
// Input  float4 idx: (b<<18)|(h<<14)|(w<<10)|(l<<4)|c4
// Output float4 idx: (b<<21)|(h<<17)|(w<<13)|(l<<7)|(n<<4)|c4

__global__ void __launch_bounds__(128) patch_neighbor_kernel(
    const float4* __restrict__ in, float4* __restrict__ out)
{
    __shared__ float4 tile[4][16][16];   // [hh][w][c4] = 16 KB

    int bid = blockIdx.x;
    int hp = bid & 7;            // h-pair index
    int l  = (bid >> 3) & 63;
    int b  = bid >> 9;
    int h0 = hp << 1;

    int t = threadIdx.x;
    const float4 zero = make_float4(0.f, 0.f, 0.f, 0.f);

    // ---- Phase 1: load 4 input rows (h0-1 .. h0+2) into SMEM, zero halo ----
    #pragma unroll
    for (int i = 0; i < 8; i++) {
        int idx = i * 128 + t;          // 0..1023
        int hh = idx >> 8;              // 0..3
        int w  = (idx >> 4) & 15;
        int c4 = idx & 15;
        int gh = h0 - 1 + hh;
        float4 v = zero;
        if ((unsigned)gh < 16u) {
            v = __ldg(&in[(b << 18) | (gh << 14) | (w << 10) | (l << 4) | c4]);
        }
        tile[hh][w][c4] = v;
    }

    __syncthreads();

    // ---- Phase 2: emit 2 output rows x 16 w x 8 n x 16 c4 from SMEM ----
    // flat = j*128 + t decodes so that per-thread: n=(t>>4)&7, c4=t&15;
    // per-iteration: hrel=j>>4, w=j&15.
    int n  = (t >> 4) & 7;
    int c4 = t & 15;

    int m  = n + (n >= 4 ? 1 : 0);      // skip 3x3 center
    int dy = m / 3 - 1;
    int dx = m % 3 - 1;

    #pragma unroll
    for (int j = 0; j < 32; j++) {
        int hrel = j >> 4;              // compile-time per unrolled j
        int w    = j & 15;              // compile-time per unrolled j

        int sh = hrel + 1 + dy;         // 0..3, always in-bounds
        int sw = w + dx;                // -1..16
        int swc = min(15, max(0, sw));

        float4 v = tile[sh][swc][c4];
        if ((unsigned)sw >= 16u) v = zero;

        int oidx = (b << 21) | ((h0 + hrel) << 17) | (w << 13)
                 | (l << 7) | (n << 4) | c4;
        __stcs(&out[oidx], v);
    }
}

extern "C" void kernel_launch(void* const* d_in, const int* in_sizes, int n_in,
                              void* d_out, int out_size)
{
    const float4* in = (const float4*)d_in[0];
    float4* out = (float4*)d_out;

    int grid = 8 * 64 * 8;   // (b, l, h-pair) = 4096 blocks
    patch_neighbor_kernel<<<grid, 128>>>(in, out);
}